// round 5
// baseline (speedup 1.0000x reference)
#include <cuda_runtime.h>

// Problem constants (from reference): B=32, T=168, M=1024, A=8, H=64, O=1
#define Mu   1024
#define Au   8
#define Hu   64

// Coefficient tables (SoA for coalesced per-warp access in the fused kernel):
//   g_u0[m] = (u0,u1,u2,u3)
//   g_u1[m] = (u4,u5,u6,u7)
//   g_c [m] = (c_mn, c_mx, c_const, 0)
// where u[a]   = sum_h assoc_w[m,a,h] * dense_w[m,h]
//       v      = sum_h assoc_b[m,h]   * dense_w[m,h]
//       s      = sum_h dense_w[m,h]
//       U      = sum_a u[a]
//       c_mn   = s - U - v ;  c_mx = v ;  c_const = dense_b[m]
// out = dot(xt,u) + mn*c_mn + mx*c_mx + c_const   (LSTM state is dead code;
// the /(mx-mn) and *(mx-mn) cancel algebraically).
__device__ float4 g_u0[Mu];
__device__ float4 g_u1[Mu];
__device__ float4 g_c [Mu];

__device__ __forceinline__ float warp_sum(float v) {
    #pragma unroll
    for (int off = 16; off > 0; off >>= 1)
        v += __shfl_xor_sync(0xffffffffu, v, off);
    return v;
}

// One warp per map-unit m. Each lane covers 2 h-values via float2 loads.
// 8 warps/block -> 128 blocks. All 10 reductions run with full ILP.
// Calls the PDL trigger after its coefficient stores so the fused kernel's
// grid can begin launching (and prefetching x) while this kernel drains.
__global__ void __launch_bounds__(256)
precompute_kernel(const float* __restrict__ assoc_w,   // [M,A,H]
                  const float* __restrict__ assoc_b,   // [M,H]
                  const float* __restrict__ dense_w,   // [M,H]
                  const float* __restrict__ dense_b) { // [M]
    const int warp = threadIdx.x >> 5;
    const int lane = threadIdx.x & 31;
    const int m = blockIdx.x * 8 + warp;   // grid = 128, 8 warps/block

    const float2 d  = reinterpret_cast<const float2*>(dense_w + m * Hu)[lane];
    const float2 ab = reinterpret_cast<const float2*>(assoc_b + m * Hu)[lane];

    float vals[10];
    #pragma unroll
    for (int a = 0; a < Au; a++) {
        const float2 w = reinterpret_cast<const float2*>(
            assoc_w + ((size_t)m * Au + a) * Hu)[lane];
        vals[a] = w.x * d.x + w.y * d.y;
    }
    vals[8] = ab.x * d.x + ab.y * d.y;   // v partial
    vals[9] = d.x + d.y;                 // s partial

    #pragma unroll
    for (int i = 0; i < 10; i++)
        vals[i] = warp_sum(vals[i]);

    if (lane == 0) {
        float U = vals[0] + vals[1] + vals[2] + vals[3]
                + vals[4] + vals[5] + vals[6] + vals[7];
        g_u0[m] = make_float4(vals[0], vals[1], vals[2], vals[3]);
        g_u1[m] = make_float4(vals[4], vals[5], vals[6], vals[7]);
        g_c [m] = make_float4(vals[9] - U - vals[8], vals[8],
                              dense_b[m], 0.0f);
    }

    // All coefficient writes in this block precede the trigger -> visible to
    // the secondary kernel after its cudaGridDependencySynchronize().
    cudaTriggerProgrammaticLaunchCompletion();
}

// 1 element per thread. Block b covers idx [b*256, b*256+256), so
// m = m_base + threadIdx.x with m_base = (b*256) & 1023 -> all three
// coefficient loads are perfectly coalesced (consecutive float4 per lane).
// PDL secondary: prefetch the streaming x loads, THEN wait on the primary.
// n = 5,505,024 is an exact multiple of 256 -> no bounds check.
__global__ void __launch_bounds__(256)
fused_kernel(const float* __restrict__ x,   // [B,T,M,A] contiguous
             float* __restrict__ out) {     // [B,T,M]
    const int idx = blockIdx.x * blockDim.x + threadIdx.x;
    const int m   = (blockIdx.x << 8 & (Mu - 1)) + threadIdx.x;

    const float4* xp = reinterpret_cast<const float4*>(x) + (size_t)idx * 2;
    const float4 a = __ldcs(xp);            // issued before the dependency wait
    const float4 b = __ldcs(xp + 1);

    cudaGridDependencySynchronize();        // coefficient tables now valid

    const float4 u0 = g_u0[m];              // coalesced: lane t -> element m_base+t
    const float4 u1 = g_u1[m];
    const float4 c  = g_c [m];

    float mn = fminf(fminf(fminf(a.x, a.y), fminf(a.z, a.w)),
                     fminf(fminf(b.x, b.y), fminf(b.z, b.w)));
    float mx = fmaxf(fmaxf(fmaxf(a.x, a.y), fmaxf(a.z, a.w)),
                     fmaxf(fmaxf(b.x, b.y), fmaxf(b.z, b.w)));

    float dot = a.x * u0.x + a.y * u0.y + a.z * u0.z + a.w * u0.w
              + b.x * u1.x + b.y * u1.y + b.z * u1.z + b.w * u1.w;

    __stcs(out + idx, dot + mn * c.x + mx * c.y + c.z);
}

extern "C" void kernel_launch(void* const* d_in, const int* in_sizes, int n_in,
                              void* d_out, int out_size) {
    // metadata order: input, assoc_w, assoc_b, w_ih, w_hh, b_ih, b_hh, dense_w, dense_b
    const float* x        = (const float*)d_in[0];
    const float* assoc_w  = (const float*)d_in[1];
    const float* assoc_b  = (const float*)d_in[2];
    const float* dense_w  = (const float*)d_in[7];
    const float* dense_b  = (const float*)d_in[8];
    float* out            = (float*)d_out;

    precompute_kernel<<<Mu / 8, 256>>>(assoc_w, assoc_b, dense_w, dense_b);

    const int n = out_size;                 // B*T*M = 5,505,024 = 21504 * 256
    const int threads = 256;
    const int blocks = n / threads;         // 21504

    // PDL: fused kernel may begin before precompute fully completes; the
    // device-side cudaGridDependencySynchronize() orders the coef reads.
    cudaLaunchConfig_t cfg = {};
    cfg.gridDim  = dim3(blocks, 1, 1);
    cfg.blockDim = dim3(threads, 1, 1);
    cfg.dynamicSmemBytes = 0;
    cfg.stream = 0;
    cudaLaunchAttribute attr[1];
    attr[0].id = cudaLaunchAttributeProgrammaticStreamSerialization;
    attr[0].val.programmaticStreamSerializationAllowed = 1;
    cfg.attrs = attr;
    cfg.numAttrs = 1;
    cudaLaunchKernelEx(&cfg, fused_kernel, x, out);
}